// round 4
// baseline (speedup 1.0000x reference)
#include <cuda_runtime.h>
#include <math.h>

#define HW 262144   // 512*512

// ---------------- scratch (device globals; no allocation allowed) -------------
__device__ float g_qkv  [2*144*HW];   // after 1x1 conv            (302 MB)
__device__ float g_dwo  [2*144*HW];   // after depthwise 3x3       (302 MB)
__device__ float g_ao   [2*48*HW];    // attn @ v, image layout    (100 MB)
__device__ float g_inv  [2*2*48*16];  // 1/max(norm,eps): [b][q/k][ch][phase]
__device__ float g_gram [2*8*96*96];  // raw q.k^T gram
__device__ float g_attnT[2*8*96*96];  // softmaxed attention, TRANSPOSED [d][r]

// ---------------- zero gram accumulator --------------------------------------
__global__ void k_zero() {
    int i = blockIdx.x * 256 + threadIdx.x;
    if (i < 2*8*96*96) g_gram[i] = 0.f;
}

// ---------------- 1x1 conv as SGEMM: out[ocTot,HW] = W[ocTot,48] @ in[48,HW] --
// grid (2048, ocTot/48, 2), block 128.  CTA tile 48 oc x 128 px, microtile 6x8.
__global__ __launch_bounds__(128) void k_conv1x1(const float* __restrict__ in,
                                                 const float* __restrict__ wgt,
                                                 float* __restrict__ out,
                                                 int ocTot) {
    __shared__ float s_x[48*128];
    __shared__ float s_w[48*48];
    const int tid = threadIdx.x;
    const int px0 = blockIdx.x * 128;
    const int ocb = blockIdx.y * 48;
    const int b   = blockIdx.z;
    const float* inb = in + (size_t)b * 48 * HW;

    // weights transposed: s_w[cin][oc_local]
    for (int i = tid; i < 48*48; i += 128) {
        int oc = i / 48, ci = i - oc*48;
        s_w[ci*48 + oc] = wgt[(ocb + oc)*48 + ci];
    }
    // x tile: s_x[cin][128], float4 coalesced
    for (int i = tid; i < 48*32; i += 128) {
        int ci = i >> 5, p4 = i & 31;
        ((float4*)s_x)[i] = ((const float4*)(inb + (size_t)ci*HW + px0))[p4];
    }
    __syncthreads();

    const int ty = tid >> 4, tx = tid & 15;
    float acc[6][8];
#pragma unroll
    for (int i = 0; i < 6; i++)
#pragma unroll
        for (int j = 0; j < 8; j++) acc[i][j] = 0.f;

    for (int ci = 0; ci < 48; ci++) {
        float wv[6], xv[8];
#pragma unroll
        for (int i = 0; i < 6; i++) wv[i] = s_w[ci*48 + ty*6 + i];
#pragma unroll
        for (int j = 0; j < 8; j++) xv[j] = s_x[ci*128 + tx + j*16];
#pragma unroll
        for (int i = 0; i < 6; i++)
#pragma unroll
            for (int j = 0; j < 8; j++) acc[i][j] += wv[i] * xv[j];
    }

#pragma unroll
    for (int i = 0; i < 6; i++) {
        float* op = out + ((size_t)b*ocTot + ocb + ty*6 + i)*HW + px0;
#pragma unroll
        for (int j = 0; j < 8; j++) op[tx + j*16] = acc[i][j];
    }
}

// ---------------- depthwise 3x3, zero pad 1 ----------------------------------
// grid (512, 144, 2), block 256
__global__ __launch_bounds__(256) void k_dw(const float* __restrict__ dww) {
    const int y  = blockIdx.x;
    const int ch = blockIdx.y;
    const int b  = blockIdx.z;
    const float* in  = g_qkv + (size_t)(b*144 + ch) * HW;
    float*       out = g_dwo + (size_t)(b*144 + ch) * HW;
    float w[9];
#pragma unroll
    for (int i = 0; i < 9; i++) w[i] = dww[ch*9 + i];

    for (int x = threadIdx.x; x < 512; x += 256) {
        float acc = 0.f;
#pragma unroll
        for (int dy = -1; dy <= 1; dy++) {
            int yy = y + dy;
            if (yy < 0 || yy >= 512) continue;
#pragma unroll
            for (int dx = -1; dx <= 1; dx++) {
                int xx = x + dx;
                if (xx < 0 || xx >= 512) continue;
                acc += w[(dy+1)*3 + (dx+1)] * in[yy*512 + xx];
            }
        }
        out[y*512 + x] = acc;
    }
}

// ---------------- per-row inverse norms (phase-binned sums of squares) -------
// grid 192 = 2 b * 96 (ch<48: q, ch>=48: k), block 256
__global__ __launch_bounds__(256) void k_norm() {
    __shared__ float s[16*256];
    const int bc = blockIdx.x;
    const int b = bc / 96, ch = bc % 96;
    const float* in = g_dwo + (size_t)(b*144 + ch) * HW;
    const int tid = threadIdx.x;

    float acc[4][4];
#pragma unroll
    for (int i = 0; i < 4; i++)
#pragma unroll
        for (int j = 0; j < 4; j++) acc[i][j] = 0.f;

    for (int i = tid; i < 65536; i += 256) {      // i indexes float4 over image
        float4 v = ((const float4*)in)[i];
        int ph = (i >> 7) & 3;                    // y%4
        acc[ph][0] += v.x*v.x; acc[ph][1] += v.y*v.y;
        acc[ph][2] += v.z*v.z; acc[ph][3] += v.w*v.w;
    }
#pragma unroll
    for (int p = 0; p < 16; p++) s[p*256 + tid] = acc[p>>2][p&3];
    __syncthreads();
    for (int ofs = 128; ofs > 0; ofs >>= 1) {
        if (tid < ofs)
            for (int p = 0; p < 16; p++) s[p*256 + tid] += s[p*256 + tid + ofs];
        __syncthreads();
    }
    if (tid < 16) {
        int qk = ch / 48, c = ch % 48;
        g_inv[((b*2 + qk)*48 + c)*16 + tid] =
            1.f / fmaxf(sqrtf(s[tid*256]), 1e-12f);
    }
}

// ---------------- gram: G[b,h,r,d] = sum_n q[r,n]k[d,n]  (split-K + atomics) --
// grid (32, 16), block 256.  CTA: 96x96 output over 512 tokens.
__global__ __launch_bounds__(256) void k_gram() {
    __shared__ float s_q[96*33], s_k[96*33];
    const int bh = blockIdx.y;
    const int b = bh >> 3, h = bh & 7;
    const int n_base = blockIdx.x * 512;
    const int tid = threadIdx.x;
    const int ty = tid >> 4, tx = tid & 15;
    const float* qbase = g_dwo + (size_t)(b*144      + h*6) * HW;
    const float* kbase = g_dwo + (size_t)(b*144 + 48 + h*6) * HW;

    float acc[6][6];
#pragma unroll
    for (int i = 0; i < 6; i++)
#pragma unroll
        for (int j = 0; j < 6; j++) acc[i][j] = 0.f;

    for (int c0 = 0; c0 < 512; c0 += 32) {
        for (int idx = tid; idx < 96*32; idx += 256) {
            int r = idx >> 5, j = idx & 31;
            int n = n_base + c0 + j;
            int ci = r >> 4, ph = r & 15;
            int H = ((n >> 7) << 2) + (ph >> 2);
            int Wp = ((n & 127) << 2) + (ph & 3);
            size_t off = (size_t)ci*HW + H*512 + Wp;
            s_q[r*33 + j] = qbase[off];
            s_k[r*33 + j] = kbase[off];
        }
        __syncthreads();
#pragma unroll 4
        for (int j = 0; j < 32; j++) {
            float qv[6], kv[6];
#pragma unroll
            for (int i = 0; i < 6; i++) qv[i] = s_q[(ty*6 + i)*33 + j];
#pragma unroll
            for (int i = 0; i < 6; i++) kv[i] = s_k[(tx*6 + i)*33 + j];
#pragma unroll
            for (int i = 0; i < 6; i++)
#pragma unroll
                for (int jj = 0; jj < 6; jj++) acc[i][jj] += qv[i] * kv[jj];
        }
        __syncthreads();
    }
    float* gp = g_gram + (size_t)bh * 96 * 96;
#pragma unroll
    for (int i = 0; i < 6; i++)
#pragma unroll
        for (int j = 0; j < 6; j++)
            atomicAdd(&gp[(ty*6 + i)*96 + tx*6 + j], acc[i][j]);
}

// ---------------- softmax (fused norm rescale + temperature) -----------------
// grid 192, block 256 (8 warps): one warp per (b,h,r) row of 96
__global__ __launch_bounds__(256) void k_soft(const float* __restrict__ temp) {
    const int warp = blockIdx.x * 8 + (threadIdx.x >> 5);  // 0..1535
    const int lane = threadIdx.x & 31;
    const int r = warp % 96, bh = warp / 96;
    const int b = bh >> 3, h = bh & 7;
    const float t = temp[h];
    const float invq = g_inv[((b*2 + 0)*48 + h*6 + (r >> 4))*16 + (r & 15)];
    const float* gp = g_gram + (size_t)bh*96*96 + (size_t)r*96;

    float v[3];
    float mx = -1e30f;
#pragma unroll
    for (int j = 0; j < 3; j++) {
        int d = lane + j*32;
        float invk = g_inv[((b*2 + 1)*48 + h*6 + (d >> 4))*16 + (d & 15)];
        v[j] = gp[d] * invq * invk * t;
        mx = fmaxf(mx, v[j]);
    }
#pragma unroll
    for (int o = 16; o > 0; o >>= 1) mx = fmaxf(mx, __shfl_xor_sync(0xffffffffu, mx, o));
    float sum = 0.f;
#pragma unroll
    for (int j = 0; j < 3; j++) { v[j] = __expf(v[j] - mx); sum += v[j]; }
#pragma unroll
    for (int o = 16; o > 0; o >>= 1) sum += __shfl_xor_sync(0xffffffffu, sum, o);
    float inv = 1.f / sum;
    float* ap = g_attnT + (size_t)bh * 96 * 96;
#pragma unroll
    for (int j = 0; j < 3; j++) {
        int d = lane + j*32;
        ap[d*96 + r] = v[j] * inv;       // transposed store [d][r]
    }
}

// ---------------- out[r,n] = sum_d attn[r,d] v[d,n], back to image layout ----
// grid (64, 16), block 256: one thread = one token n (a 4x4 pixel block)
__global__ __launch_bounds__(256) void k_attnv() {
    __shared__ float s_a[96*96];  // [d][r]
    const int bh = blockIdx.y;
    const int b = bh >> 3, h = bh & 7;
    const int tid = threadIdx.x;
    const float* ap = g_attnT + (size_t)bh * 96 * 96;
    for (int i = tid; i < 96*96/4; i += 256)
        ((float4*)s_a)[i] = ((const float4*)ap)[i];
    __syncthreads();

    const int n  = blockIdx.x * 256 + tid;
    const int H0 = (n >> 7) << 2;
    const int W0 = (n & 127) << 2;
    const float* vbase = g_dwo + (size_t)(b*144 + 96 + h*6) * HW;

    float4 v[6][4];
#pragma unroll
    for (int ci = 0; ci < 6; ci++)
#pragma unroll
        for (int hh = 0; hh < 4; hh++)
            v[ci][hh] = *(const float4*)(vbase + (size_t)ci*HW + (H0 + hh)*512 + W0);

    float* obase = g_ao + (size_t)(b*48 + h*6) * HW;
#pragma unroll 1
    for (int ci = 0; ci < 6; ci++) {
#pragma unroll 1
        for (int Nh = 0; Nh < 4; Nh++) {
            const int r0 = ci*16 + Nh*4;
            float4 acc = make_float4(0.f, 0.f, 0.f, 0.f);
#pragma unroll
            for (int cj = 0; cj < 6; cj++) {
#pragma unroll
                for (int h2 = 0; h2 < 4; h2++) {
                    float4 vv = v[cj][h2];
                    const int d0 = cj*16 + h2*4;
                    float4 a;
                    a = *(const float4*)&s_a[(d0+0)*96 + r0];
                    acc.x += a.x*vv.x; acc.y += a.y*vv.x; acc.z += a.z*vv.x; acc.w += a.w*vv.x;
                    a = *(const float4*)&s_a[(d0+1)*96 + r0];
                    acc.x += a.x*vv.y; acc.y += a.y*vv.y; acc.z += a.z*vv.y; acc.w += a.w*vv.y;
                    a = *(const float4*)&s_a[(d0+2)*96 + r0];
                    acc.x += a.x*vv.z; acc.y += a.y*vv.z; acc.z += a.z*vv.z; acc.w += a.w*vv.z;
                    a = *(const float4*)&s_a[(d0+3)*96 + r0];
                    acc.x += a.x*vv.w; acc.y += a.y*vv.w; acc.z += a.z*vv.w; acc.w += a.w*vv.w;
                }
            }
            *(float4*)(obase + (size_t)ci*HW + (H0 + Nh)*512 + W0) = acc;
        }
    }
}

// ---------------- launch -----------------------------------------------------
extern "C" void kernel_launch(void* const* d_in, const int* in_sizes, int n_in,
                              void* d_out, int out_size) {
    const float* x      = (const float*)d_in[0];
    const float* qkv_w  = (const float*)d_in[1];
    const float* dw_w   = (const float*)d_in[2];
    const float* proj_w = (const float*)d_in[3];
    const float* temp   = (const float*)d_in[4];
    float* out = (float*)d_out;
    (void)in_sizes; (void)n_in; (void)out_size;

    void *p_qkv, *p_ao;
    cudaGetSymbolAddress(&p_qkv, g_qkv);
    cudaGetSymbolAddress(&p_ao,  g_ao);

    k_zero<<<(2*8*96*96 + 255)/256, 256>>>();
    k_conv1x1<<<dim3(2048, 3, 2), 128>>>(x, qkv_w, (float*)p_qkv, 144);
    k_dw<<<dim3(512, 144, 2), 256>>>(dw_w);
    k_norm<<<192, 256>>>();
    k_gram<<<dim3(32, 16), 256>>>();
    k_soft<<<192, 256>>>(temp);
    k_attnv<<<dim3(64, 16), 256>>>();
    k_conv1x1<<<dim3(2048, 1, 2), 128>>>((const float*)p_ao, proj_w, out, 48);
}

// round 6
// speedup vs baseline: 1.4041x; 1.4041x over previous
#include <cuda_runtime.h>
#include <math.h>

#define HW 262144   // 512*512
typedef unsigned long long u64;

// ---------------- packed f32x2 helpers (sm_103a FFMA2) ------------------------
__device__ __forceinline__ u64 pk(float lo, float hi) {
    u64 r;
    asm("mov.b64 %0, {%1, %2};" : "=l"(r) : "f"(lo), "f"(hi));
    return r;
}
__device__ __forceinline__ void fma2(u64& d, u64 a, u64 b) {
    asm("fma.rn.f32x2 %0, %1, %2, %0;" : "+l"(d) : "l"(a), "l"(b));
}
__device__ __forceinline__ float2 upk(u64 v) {
    float2 f;
    asm("mov.b64 {%0, %1}, %2;" : "=f"(f.x), "=f"(f.y) : "l"(v));
    return f;
}

// ---------------- scratch (device globals; no allocation allowed) -------------
__device__ float g_qkv  [2*144*HW];   // after 1x1 conv
__device__ float g_dwo  [2*144*HW];   // after depthwise 3x3
__device__ float g_ao   [2*48*HW];    // attn @ v, image layout
__device__ float g_sq   [2*2*48*16];  // sum of squares: [b][q/k][ch][phase]
__device__ float g_gram [2*8*96*96];  // raw q.k^T gram
__device__ float g_attnT[2*8*96*96];  // softmaxed attention, TRANSPOSED [d][r]

// ---------------- zero accumulators -------------------------------------------
__global__ void k_zero() {
    int i = blockIdx.x * 256 + threadIdx.x;
    if (i < 2*8*96*96) g_gram[i] = 0.f;
    if (i < 2*2*48*16) g_sq[i]   = 0.f;
}

// ---------------- 1x1 conv as SGEMM (f32x2): out[ocTot,HW]=W[ocTot,48]@in -----
// grid (2048, ocTot/48, 2), block 128.  CTA tile 48 oc x 128 px, microtile 6x8.
__global__ __launch_bounds__(128) void k_conv1x1(const float* __restrict__ in,
                                                 const float* __restrict__ wgt,
                                                 float* __restrict__ out,
                                                 int ocTot) {
    __shared__ __align__(16) float s_x[48*128];
    __shared__ float s_w[48*48];
    const int tid = threadIdx.x;
    const int px0 = blockIdx.x * 128;
    const int ocb = blockIdx.y * 48;
    const int b   = blockIdx.z;
    const float* inb = in + (size_t)b * 48 * HW;

    for (int i = tid; i < 48*48; i += 128) {
        int oc = i / 48, ci = i - oc*48;
        s_w[ci*48 + oc] = wgt[(ocb + oc)*48 + ci];
    }
    for (int i = tid; i < 48*32; i += 128) {
        int ci = i >> 5, p4 = i & 31;
        ((float4*)s_x)[i] = ((const float4*)(inb + (size_t)ci*HW + px0))[p4];
    }
    __syncthreads();

    const int ty = tid >> 4, tx = tid & 15;   // ty 0..7 (6 oc), tx 0..15 (2px x4)
    u64 acc2[6][4];
#pragma unroll
    for (int i = 0; i < 6; i++)
#pragma unroll
        for (int j = 0; j < 4; j++) acc2[i][j] = pk(0.f, 0.f);

    for (int ci = 0; ci < 48; ci++) {
        u64 wp[6], xv[4];
#pragma unroll
        for (int i = 0; i < 6; i++) {
            float wv = s_w[ci*48 + ty*6 + i];
            wp[i] = pk(wv, wv);
        }
#pragma unroll
        for (int j = 0; j < 4; j++)
            xv[j] = *(const u64*)&s_x[ci*128 + tx*2 + j*32];
#pragma unroll
        for (int i = 0; i < 6; i++)
#pragma unroll
            for (int j = 0; j < 4; j++) fma2(acc2[i][j], wp[i], xv[j]);
    }

#pragma unroll
    for (int i = 0; i < 6; i++) {
        float* op = out + ((size_t)b*ocTot + ocb + ty*6 + i)*HW + px0;
#pragma unroll
        for (int j = 0; j < 4; j++)
            *(float2*)(op + tx*2 + j*32) = upk(acc2[i][j]);
    }
}

// ---------------- depthwise 3x3 (zero pad) + fused phase sum-of-squares -------
// grid (512, 144, 2), block 128: each thread one float4 output
__global__ __launch_bounds__(128) void k_dw(const float* __restrict__ dww) {
    __shared__ float s_red[4][4];
    const int y  = blockIdx.x;
    const int ch = blockIdx.y;
    const int b  = blockIdx.z;
    const float* in  = g_qkv + (size_t)(b*144 + ch) * HW;
    float*       out = g_dwo + (size_t)(b*144 + ch) * HW;
    float w[9];
#pragma unroll
    for (int i = 0; i < 9; i++) w[i] = dww[ch*9 + i];

    const int x4 = threadIdx.x * 4;
    float o0 = 0.f, o1 = 0.f, o2 = 0.f, o3 = 0.f;
#pragma unroll
    for (int dy = -1; dy <= 1; dy++) {
        int yy = y + dy;
        if (yy < 0 || yy >= 512) continue;
        const float* row = in + yy*512;
        float4 c = *(const float4*)(row + x4);
        float l = (x4 > 0)   ? row[x4 - 1] : 0.f;
        float r = (x4 < 508) ? row[x4 + 4] : 0.f;
        float w0 = w[(dy+1)*3], w1 = w[(dy+1)*3 + 1], w2 = w[(dy+1)*3 + 2];
        o0 += w0*l   + w1*c.x + w2*c.y;
        o1 += w0*c.x + w1*c.y + w2*c.z;
        o2 += w0*c.y + w1*c.z + w2*c.w;
        o3 += w0*c.z + w1*c.w + w2*r;
    }
    *(float4*)(out + y*512 + x4) = make_float4(o0, o1, o2, o3);

    if (ch < 96) {   // q or k channel: accumulate per-phase sum of squares
        float s0 = o0*o0, s1 = o1*o1, s2 = o2*o2, s3 = o3*o3;
#pragma unroll
        for (int o = 16; o > 0; o >>= 1) {
            s0 += __shfl_xor_sync(0xffffffffu, s0, o);
            s1 += __shfl_xor_sync(0xffffffffu, s1, o);
            s2 += __shfl_xor_sync(0xffffffffu, s2, o);
            s3 += __shfl_xor_sync(0xffffffffu, s3, o);
        }
        int warp = threadIdx.x >> 5, lane = threadIdx.x & 31;
        if (lane == 0) {
            s_red[warp][0] = s0; s_red[warp][1] = s1;
            s_red[warp][2] = s2; s_red[warp][3] = s3;
        }
        __syncthreads();
        if (threadIdx.x < 4) {
            float v = s_red[0][threadIdx.x] + s_red[1][threadIdx.x]
                    + s_red[2][threadIdx.x] + s_red[3][threadIdx.x];
            int qk = ch / 48, cc = ch - qk*48;
            atomicAdd(&g_sq[((b*2 + qk)*48 + cc)*16 + (y & 3)*4 + threadIdx.x], v);
        }
    }
}

// ---------------- gram: G[b,h,r,d] = sum_n q[r,n]k[d,n]  (split-K, f32x2) -----
// grid (32, 16), block 256.  CTA: 96x96 output over 512 tokens.
__global__ __launch_bounds__(256) void k_gram() {
    __shared__ float s_q[96*33];
    __shared__ __align__(16) float s_kT[32*98];   // [j][d] transposed, pad 98
    const int bh = blockIdx.y;
    const int b = bh >> 3, h = bh & 7;
    const int n_base = blockIdx.x * 512;
    const int tid = threadIdx.x;
    const int ty = tid >> 4, tx = tid & 15;
    const float* qbase = g_dwo + (size_t)(b*144      + h*6) * HW;
    const float* kbase = g_dwo + (size_t)(b*144 + 48 + h*6) * HW;

    u64 acc2[6][3];
#pragma unroll
    for (int i = 0; i < 6; i++)
#pragma unroll
        for (int m = 0; m < 3; m++) acc2[i][m] = pk(0.f, 0.f);

    for (int c0 = 0; c0 < 512; c0 += 32) {
        for (int idx = tid; idx < 96*32; idx += 256) {
            int r = idx >> 5, j = idx & 31;
            int n = n_base + c0 + j;
            int ci = r >> 4, ph = r & 15;
            int H  = ((n >> 7) << 2) + (ph >> 2);
            int Wp = ((n & 127) << 2) + (ph & 3);
            size_t off = (size_t)ci*HW + H*512 + Wp;
            s_q [r*33 + j] = qbase[off];
            s_kT[j*98 + r] = kbase[off];
        }
        __syncthreads();
#pragma unroll 4
        for (int j = 0; j < 32; j++) {
            u64 qp[6], kv[3];
#pragma unroll
            for (int i = 0; i < 6; i++) {
                float qv = s_q[(ty*6 + i)*33 + j];
                qp[i] = pk(qv, qv);
            }
#pragma unroll
            for (int m = 0; m < 3; m++)
                kv[m] = *(const u64*)&s_kT[j*98 + tx*6 + 2*m];
#pragma unroll
            for (int i = 0; i < 6; i++)
#pragma unroll
                for (int m = 0; m < 3; m++) fma2(acc2[i][m], qp[i], kv[m]);
        }
        __syncthreads();
    }
    float* gp = g_gram + (size_t)bh * 96 * 96;
#pragma unroll
    for (int i = 0; i < 6; i++)
#pragma unroll
        for (int m = 0; m < 3; m++) {
            float2 v = upk(acc2[i][m]);
            atomicAdd(&gp[(ty*6 + i)*96 + tx*6 + 2*m    ], v.x);
            atomicAdd(&gp[(ty*6 + i)*96 + tx*6 + 2*m + 1], v.y);
        }
}

// ---------------- softmax (fused norm rescale + temperature) -----------------
// grid 192, block 256 (8 warps): one warp per (b,h,r) row of 96
__global__ __launch_bounds__(256) void k_soft(const float* __restrict__ temp) {
    const int warp = blockIdx.x * 8 + (threadIdx.x >> 5);  // 0..1535
    const int lane = threadIdx.x & 31;
    const int r = warp % 96, bh = warp / 96;
    const int b = bh >> 3, h = bh & 7;
    const float t = temp[h];
    float sqq = g_sq[((b*2 + 0)*48 + h*6 + (r >> 4))*16 + (r & 15)];
    const float invq = 1.f / fmaxf(sqrtf(sqq), 1e-12f);
    const float* gp = g_gram + (size_t)bh*96*96 + (size_t)r*96;

    float v[3];
    float mx = -1e30f;
#pragma unroll
    for (int j = 0; j < 3; j++) {
        int d = lane + j*32;
        float sqk = g_sq[((b*2 + 1)*48 + h*6 + (d >> 4))*16 + (d & 15)];
        float invk = 1.f / fmaxf(sqrtf(sqk), 1e-12f);
        v[j] = gp[d] * invq * invk * t;
        mx = fmaxf(mx, v[j]);
    }
#pragma unroll
    for (int o = 16; o > 0; o >>= 1) mx = fmaxf(mx, __shfl_xor_sync(0xffffffffu, mx, o));
    float sum = 0.f;
#pragma unroll
    for (int j = 0; j < 3; j++) { v[j] = __expf(v[j] - mx); sum += v[j]; }
#pragma unroll
    for (int o = 16; o > 0; o >>= 1) sum += __shfl_xor_sync(0xffffffffu, sum, o);
    float inv = 1.f / sum;
    float* ap = g_attnT + (size_t)bh * 96 * 96;
#pragma unroll
    for (int j = 0; j < 3; j++) {
        int d = lane + j*32;
        ap[d*96 + r] = v[j] * inv;       // transposed store [d][r]
    }
}

// ---------------- out[r,n] = sum_d attn[r,d] v[d,n] (f32x2) ------------------
// grid (64, 16), block 256: one thread = one token n (a 4x4 pixel block)
__global__ __launch_bounds__(256) void k_attnv() {
    __shared__ __align__(16) float s_a[96*96];  // [d][r]
    const int bh = blockIdx.y;
    const int b = bh >> 3, h = bh & 7;
    const int tid = threadIdx.x;
    const float* ap = g_attnT + (size_t)bh * 96 * 96;
    for (int i = tid; i < 96*96/4; i += 256)
        ((float4*)s_a)[i] = ((const float4*)ap)[i];
    __syncthreads();

    const int n  = blockIdx.x * 256 + tid;
    const int H0 = (n >> 7) << 2;
    const int W0 = (n & 127) << 2;
    const float* vbase = g_dwo + (size_t)(b*144 + 96 + h*6) * HW;

    float4 v[6][4];
#pragma unroll
    for (int ci = 0; ci < 6; ci++)
#pragma unroll
        for (int hh = 0; hh < 4; hh++)
            v[ci][hh] = *(const float4*)(vbase + (size_t)ci*HW + (H0 + hh)*512 + W0);

    float* obase = g_ao + (size_t)(b*48 + h*6) * HW;
#pragma unroll 1
    for (int ci = 0; ci < 6; ci++) {
#pragma unroll 1
        for (int Nh = 0; Nh < 4; Nh++) {
            const int r0 = ci*16 + Nh*4;
            u64 accL = pk(0.f, 0.f), accH = pk(0.f, 0.f);
#pragma unroll
            for (int cj = 0; cj < 6; cj++) {
#pragma unroll
                for (int h2 = 0; h2 < 4; h2++) {
                    float4 vv = v[cj][h2];
                    const int d0 = cj*16 + h2*4;
                    ulonglong2 A; u64 vp;
                    A = *(const ulonglong2*)&s_a[(d0+0)*96 + r0];
                    vp = pk(vv.x, vv.x); fma2(accL, A.x, vp); fma2(accH, A.y, vp);
                    A = *(const ulonglong2*)&s_a[(d0+1)*96 + r0];
                    vp = pk(vv.y, vv.y); fma2(accL, A.x, vp); fma2(accH, A.y, vp);
                    A = *(const ulonglong2*)&s_a[(d0+2)*96 + r0];
                    vp = pk(vv.z, vv.z); fma2(accL, A.x, vp); fma2(accH, A.y, vp);
                    A = *(const ulonglong2*)&s_a[(d0+3)*96 + r0];
                    vp = pk(vv.w, vv.w); fma2(accL, A.x, vp); fma2(accH, A.y, vp);
                }
            }
            float2 lo = upk(accL), hi = upk(accH);
            *(float4*)(obase + (size_t)ci*HW + (H0 + Nh)*512 + W0) =
                make_float4(lo.x, lo.y, hi.x, hi.y);
        }
    }
}

// ---------------- launch -----------------------------------------------------
extern "C" void kernel_launch(void* const* d_in, const int* in_sizes, int n_in,
                              void* d_out, int out_size) {
    const float* x      = (const float*)d_in[0];
    const float* qkv_w  = (const float*)d_in[1];
    const float* dw_w   = (const float*)d_in[2];
    const float* proj_w = (const float*)d_in[3];
    const float* temp   = (const float*)d_in[4];
    float* out = (float*)d_out;
    (void)in_sizes; (void)n_in; (void)out_size;

    void *p_qkv, *p_ao;
    cudaGetSymbolAddress(&p_qkv, g_qkv);
    cudaGetSymbolAddress(&p_ao,  g_ao);

    k_zero<<<(2*8*96*96 + 255)/256, 256>>>();
    k_conv1x1<<<dim3(2048, 3, 2), 128>>>(x, qkv_w, (float*)p_qkv, 144);
    k_dw<<<dim3(512, 144, 2), 128>>>(dw_w);
    k_gram<<<dim3(32, 16), 256>>>();
    k_soft<<<192, 256>>>(temp);
    k_attnv<<<dim3(64, 16), 256>>>();
    k_conv1x1<<<dim3(2048, 1, 2), 128>>>((const float*)p_ao, proj_w, out, 48);
}

// round 12
// speedup vs baseline: 1.5430x; 1.0989x over previous
#include <cuda_runtime.h>
#include <cuda_bf16.h>
#include <math.h>
#include <stdint.h>

#define HW 262144   // 512*512
typedef unsigned long long u64;

// ---------------- packed f32x2 helpers (sm_103a FFMA2) ------------------------
__device__ __forceinline__ u64 pk(float lo, float hi) {
    u64 r;
    asm("mov.b64 %0, {%1, %2};" : "=l"(r) : "f"(lo), "f"(hi));
    return r;
}
__device__ __forceinline__ void fma2(u64& d, u64 a, u64 b) {
    asm("fma.rn.f32x2 %0, %1, %2, %0;" : "+l"(d) : "l"(a), "l"(b));
}
__device__ __forceinline__ float2 upk(u64 v) {
    float2 f;
    asm("mov.b64 {%0, %1}, %2;" : "=f"(f.x), "=f"(f.y) : "l"(v));
    return f;
}

// ---------------- mma.sync helper (bf16, fp32 accum) --------------------------
__device__ __forceinline__ void mma16816(float* c, const uint32_t* a, const uint32_t* b) {
    asm volatile(
        "mma.sync.aligned.m16n8k16.row.col.f32.bf16.bf16.f32 "
        "{%0,%1,%2,%3}, {%4,%5,%6,%7}, {%8,%9}, {%0,%1,%2,%3};"
        : "+f"(c[0]), "+f"(c[1]), "+f"(c[2]), "+f"(c[3])
        : "r"(a[0]), "r"(a[1]), "r"(a[2]), "r"(a[3]), "r"(b[0]), "r"(b[1]));
}

// ---------------- scratch (device globals; no allocation allowed) -------------
__device__ float g_qkv   [2*144*HW];    // after 1x1 conv
__device__ float g_dwo   [2*144*HW];    // after depthwise 3x3
__device__ float g_ao    [2*48*HW];     // attn @ v, image layout
__device__ float g_sq    [2*2*48*16];   // sum of squares: [b][q/k][ch][phase]
__device__ float g_gsplit[32*16*96*96]; // per-split partial grams [s][bh][r][d]
__device__ float g_attnT [2*8*96*96];   // softmaxed attention, TRANSPOSED [d][r]

// ---------------- zero sum-of-squares accumulator -----------------------------
__global__ void k_zero() {
    int i = blockIdx.x * 256 + threadIdx.x;
    if (i < 2*2*48*16) g_sq[i] = 0.f;
}

// ---------------- 1x1 conv as SGEMM (f32x2) -----------------------------------
__global__ __launch_bounds__(128) void k_conv1x1(const float* __restrict__ in,
                                                 const float* __restrict__ wgt,
                                                 float* __restrict__ out,
                                                 int ocTot) {
    __shared__ __align__(16) float s_x[48*128];
    __shared__ float s_w[48*48];
    const int tid = threadIdx.x;
    const int px0 = blockIdx.x * 128;
    const int ocb = blockIdx.y * 48;
    const int b   = blockIdx.z;
    const float* inb = in + (size_t)b * 48 * HW;

    for (int i = tid; i < 48*48; i += 128) {
        int oc = i / 48, ci = i - oc*48;
        s_w[ci*48 + oc] = wgt[(ocb + oc)*48 + ci];
    }
    for (int i = tid; i < 48*32; i += 128) {
        int ci = i >> 5, p4 = i & 31;
        ((float4*)s_x)[i] = ((const float4*)(inb + (size_t)ci*HW + px0))[p4];
    }
    __syncthreads();

    const int ty = tid >> 4, tx = tid & 15;
    u64 acc2[6][4];
#pragma unroll
    for (int i = 0; i < 6; i++)
#pragma unroll
        for (int j = 0; j < 4; j++) acc2[i][j] = pk(0.f, 0.f);

    for (int ci = 0; ci < 48; ci++) {
        u64 wp[6], xv[4];
#pragma unroll
        for (int i = 0; i < 6; i++) {
            float wv = s_w[ci*48 + ty*6 + i];
            wp[i] = pk(wv, wv);
        }
#pragma unroll
        for (int j = 0; j < 4; j++)
            xv[j] = *(const u64*)&s_x[ci*128 + tx*2 + j*32];
#pragma unroll
        for (int i = 0; i < 6; i++)
#pragma unroll
            for (int j = 0; j < 4; j++) fma2(acc2[i][j], wp[i], xv[j]);
    }

#pragma unroll
    for (int i = 0; i < 6; i++) {
        float* op = out + ((size_t)b*ocTot + ocb + ty*6 + i)*HW + px0;
#pragma unroll
        for (int j = 0; j < 4; j++)
            *(float2*)(op + tx*2 + j*32) = upk(acc2[i][j]);
    }
}

// ---------------- depthwise 3x3 (zero pad) + fused phase sum-of-squares -------
__global__ __launch_bounds__(128) void k_dw(const float* __restrict__ dww) {
    __shared__ float s_red[4][4];
    const int y  = blockIdx.x;
    const int ch = blockIdx.y;
    const int b  = blockIdx.z;
    const float* in  = g_qkv + (size_t)(b*144 + ch) * HW;
    float*       out = g_dwo + (size_t)(b*144 + ch) * HW;
    float w[9];
#pragma unroll
    for (int i = 0; i < 9; i++) w[i] = dww[ch*9 + i];

    const int x4 = threadIdx.x * 4;
    float o0 = 0.f, o1 = 0.f, o2 = 0.f, o3 = 0.f;
#pragma unroll
    for (int dy = -1; dy <= 1; dy++) {
        int yy = y + dy;
        if (yy < 0 || yy >= 512) continue;
        const float* row = in + yy*512;
        float4 c = *(const float4*)(row + x4);
        float l = (x4 > 0)   ? row[x4 - 1] : 0.f;
        float r = (x4 < 508) ? row[x4 + 4] : 0.f;
        float w0 = w[(dy+1)*3], w1 = w[(dy+1)*3 + 1], w2 = w[(dy+1)*3 + 2];
        o0 += w0*l   + w1*c.x + w2*c.y;
        o1 += w0*c.x + w1*c.y + w2*c.z;
        o2 += w0*c.y + w1*c.z + w2*c.w;
        o3 += w0*c.z + w1*c.w + w2*r;
    }
    *(float4*)(out + y*512 + x4) = make_float4(o0, o1, o2, o3);

    if (ch < 96) {
        float s0 = o0*o0, s1 = o1*o1, s2 = o2*o2, s3 = o3*o3;
#pragma unroll
        for (int o = 16; o > 0; o >>= 1) {
            s0 += __shfl_xor_sync(0xffffffffu, s0, o);
            s1 += __shfl_xor_sync(0xffffffffu, s1, o);
            s2 += __shfl_xor_sync(0xffffffffu, s2, o);
            s3 += __shfl_xor_sync(0xffffffffu, s3, o);
        }
        int warp = threadIdx.x >> 5, lane = threadIdx.x & 31;
        if (lane == 0) {
            s_red[warp][0] = s0; s_red[warp][1] = s1;
            s_red[warp][2] = s2; s_red[warp][3] = s3;
        }
        __syncthreads();
        if (threadIdx.x < 4) {
            float v = s_red[0][threadIdx.x] + s_red[1][threadIdx.x]
                    + s_red[2][threadIdx.x] + s_red[3][threadIdx.x];
            int qk = ch / 48, cc = ch - qk*48;
            atomicAdd(&g_sq[((b*2 + qk)*48 + cc)*16 + (y & 3)*4 + threadIdx.x], v);
        }
    }
}

// ---------------- gram via mma.sync bf16 hi/lo split --------------------------
// grid (32 splits, 16 bh), block 192 (6 warps).  Warp w: rows [16w,16w+16).
// SMEM tiles: [96 rows][72 bf16] (64 tokens used, pad to 72 -> word stride 36).
#define GT_STRIDE 72                     // bf16 per row
#define GT_WORDS  36                     // 32-bit words per row
#define GT_BYTES  (96*GT_STRIDE*2)       // 13824 per tile
#define OFF_QH 0
#define OFF_QL GT_BYTES
#define OFF_KH (2*GT_BYTES)
#define OFF_KL (3*GT_BYTES)
#define GRAM_SMEM (4*GT_BYTES)           // 55296

__global__ __launch_bounds__(192) void k_gram_mma() {
    extern __shared__ char smem[];
    uint32_t* sw = (uint32_t*)smem;
    const int tid  = threadIdx.x;
    const int wid  = tid >> 5, lane = tid & 31;
    const int split = blockIdx.x;
    const int bh = blockIdx.y;
    const int b = bh >> 3, h = bh & 7;
    const float* qbase = g_dwo + (size_t)(b*144      + h*6) * HW;
    const float* kbase = g_dwo + (size_t)(b*144 + 48 + h*6) * HW;

    float acc[12][4];
#pragma unroll
    for (int t = 0; t < 12; t++)
#pragma unroll
        for (int i = 0; i < 4; i++) acc[t][i] = 0.f;

    const int g4 = lane >> 2;        // fragment row group 0..7
    const int q4 = lane & 3;         // fragment quad lane 0..3

#pragma unroll 1
    for (int chunk = 0; chunk < 8; chunk++) {
        const int n0 = split*512 + chunk*64;
        const int hb = n0 >> 7, wb = n0 & 127;

        // -------- fill: 16 float4 per thread (one float4 = 4 rows of 1 token)
        if (chunk > 0) __syncthreads();
#pragma unroll
        for (int i = 0; i < 16; i++) {
            int u = tid + i*192;                 // 0..3071
            int side = (u >= 1536) ? 1 : 0;
            int rem = u - side*1536;
            int j = rem & 63, g = rem >> 6;      // g 0..23
            int ci = g >> 2, phy = g & 3;
            const float* bp = side ? kbase : qbase;
            float4 v4 = *(const float4*)(bp + (size_t)ci*HW
                                            + (size_t)(4*hb + phy)*512 + 4*(wb + j));
            __nv_bfloat16* th = (__nv_bfloat16*)(smem + (side ? OFF_KH : OFF_QH));
            __nv_bfloat16* tl = (__nv_bfloat16*)(smem + (side ? OFF_KL : OFF_QL));
            int r0 = ci*16 + phy*4;
            float vv[4] = {v4.x, v4.y, v4.z, v4.w};
#pragma unroll
            for (int p = 0; p < 4; p++) {
                float v = vv[p];
                __nv_bfloat16 hi = __float2bfloat16(v);
                __nv_bfloat16 lo = __float2bfloat16(v - __bfloat162float(hi));
                th[(r0 + p)*GT_STRIDE + j] = hi;
                tl[(r0 + p)*GT_STRIDE + j] = lo;
            }
        }
        __syncthreads();

        // -------- compute: 4 k-steps of 16 tokens
        const uint32_t* qh = sw + (OFF_QH >> 2);
        const uint32_t* ql = sw + (OFF_QL >> 2);
        const uint32_t* kh = sw + (OFF_KH >> 2);
        const uint32_t* kl = sw + (OFF_KL >> 2);
        const int arow = wid*16 + g4;            // A rows arow, arow+8
#pragma unroll
        for (int ks = 0; ks < 4; ks++) {
            const int kw = ks*8 + q4;            // word offset in row
            uint32_t Ah[4], Al[4];
            Ah[0] = qh[ arow     *GT_WORDS + kw    ];
            Ah[1] = qh[(arow + 8)*GT_WORDS + kw    ];
            Ah[2] = qh[ arow     *GT_WORDS + kw + 4];
            Ah[3] = qh[(arow + 8)*GT_WORDS + kw + 4];
            Al[0] = ql[ arow     *GT_WORDS + kw    ];
            Al[1] = ql[(arow + 8)*GT_WORDS + kw    ];
            Al[2] = ql[ arow     *GT_WORDS + kw + 4];
            Al[3] = ql[(arow + 8)*GT_WORDS + kw + 4];
#pragma unroll
            for (int nt = 0; nt < 12; nt++) {
                const int nrow = nt*8 + g4;
                uint32_t Bh[2], Bl[2];
                Bh[0] = kh[nrow*GT_WORDS + kw    ];
                Bh[1] = kh[nrow*GT_WORDS + kw + 4];
                Bl[0] = kl[nrow*GT_WORDS + kw    ];
                Bl[1] = kl[nrow*GT_WORDS + kw + 4];
                mma16816(acc[nt], Ah, Bh);
                mma16816(acc[nt], Ah, Bl);
                mma16816(acc[nt], Al, Bh);
            }
        }
    }

    // -------- epilogue: D fragments -> per-split gram (no atomics)
    float* gp = g_gsplit + (size_t)(split*16 + bh)*96*96;
    const int r0 = wid*16 + g4;
#pragma unroll
    for (int nt = 0; nt < 12; nt++) {
        const int c = nt*8 + q4*2;
        *(float2*)(gp + (size_t) r0     *96 + c) = make_float2(acc[nt][0], acc[nt][1]);
        *(float2*)(gp + (size_t)(r0 + 8)*96 + c) = make_float2(acc[nt][2], acc[nt][3]);
    }
}

// ---------------- softmax (split-sum + norm rescale + temperature) ------------
__global__ __launch_bounds__(256) void k_soft(const float* __restrict__ temp) {
    const int warp = blockIdx.x * 8 + (threadIdx.x >> 5);
    const int lane = threadIdx.x & 31;
    const int r = warp % 96, bh = warp / 96;
    const int b = bh >> 3, h = bh & 7;
    const float t = temp[h];
    float sqq = g_sq[((b*2 + 0)*48 + h*6 + (r >> 4))*16 + (r & 15)];
    const float invq = 1.f / fmaxf(sqrtf(sqq), 1e-12f);

    float v[3];
    float mx = -1e30f;
#pragma unroll
    for (int j = 0; j < 3; j++) {
        int d = lane + j*32;
        float g = 0.f;
#pragma unroll 4
        for (int s = 0; s < 32; s++)
            g += g_gsplit[((size_t)(s*16 + bh)*96 + r)*96 + d];
        float sqk = g_sq[((b*2 + 1)*48 + h*6 + (d >> 4))*16 + (d & 15)];
        float invk = 1.f / fmaxf(sqrtf(sqk), 1e-12f);
        v[j] = g * invq * invk * t;
        mx = fmaxf(mx, v[j]);
    }
#pragma unroll
    for (int o = 16; o > 0; o >>= 1) mx = fmaxf(mx, __shfl_xor_sync(0xffffffffu, mx, o));
    float sum = 0.f;
#pragma unroll
    for (int j = 0; j < 3; j++) { v[j] = __expf(v[j] - mx); sum += v[j]; }
#pragma unroll
    for (int o = 16; o > 0; o >>= 1) sum += __shfl_xor_sync(0xffffffffu, sum, o);
    float inv = 1.f / sum;
    float* ap = g_attnT + (size_t)bh * 96 * 96;
#pragma unroll
    for (int j = 0; j < 3; j++) {
        int d = lane + j*32;
        ap[d*96 + r] = v[j] * inv;
    }
}

// ---------------- out[r,n] = sum_d attn[r,d] v[d,n] (f32x2) -------------------
__global__ __launch_bounds__(256) void k_attnv() {
    __shared__ __align__(16) float s_a[96*96];
    const int bh = blockIdx.y;
    const int b = bh >> 3, h = bh & 7;
    const int tid = threadIdx.x;
    const float* ap = g_attnT + (size_t)bh * 96 * 96;
    for (int i = tid; i < 96*96/4; i += 256)
        ((float4*)s_a)[i] = ((const float4*)ap)[i];
    __syncthreads();

    const int n  = blockIdx.x * 256 + tid;
    const int H0 = (n >> 7) << 2;
    const int W0 = (n & 127) << 2;
    const float* vbase = g_dwo + (size_t)(b*144 + 96 + h*6) * HW;

    float4 v[6][4];
#pragma unroll
    for (int ci = 0; ci < 6; ci++)
#pragma unroll
        for (int hh = 0; hh < 4; hh++)
            v[ci][hh] = *(const float4*)(vbase + (size_t)ci*HW + (H0 + hh)*512 + W0);

    float* obase = g_ao + (size_t)(b*48 + h*6) * HW;
#pragma unroll 1
    for (int ci = 0; ci < 6; ci++) {
#pragma unroll 1
        for (int Nh = 0; Nh < 4; Nh++) {
            const int r0 = ci*16 + Nh*4;
            u64 accL = pk(0.f, 0.f), accH = pk(0.f, 0.f);
#pragma unroll
            for (int cj = 0; cj < 6; cj++) {
#pragma unroll
                for (int h2 = 0; h2 < 4; h2++) {
                    float4 vv = v[cj][h2];
                    const int d0 = cj*16 + h2*4;
                    ulonglong2 A; u64 vp;
                    A = *(const ulonglong2*)&s_a[(d0+0)*96 + r0];
                    vp = pk(vv.x, vv.x); fma2(accL, A.x, vp); fma2(accH, A.y, vp);
                    A = *(const ulonglong2*)&s_a[(d0+1)*96 + r0];
                    vp = pk(vv.y, vv.y); fma2(accL, A.x, vp); fma2(accH, A.y, vp);
                    A = *(const ulonglong2*)&s_a[(d0+2)*96 + r0];
                    vp = pk(vv.z, vv.z); fma2(accL, A.x, vp); fma2(accH, A.y, vp);
                    A = *(const ulonglong2*)&s_a[(d0+3)*96 + r0];
                    vp = pk(vv.w, vv.w); fma2(accL, A.x, vp); fma2(accH, A.y, vp);
                }
            }
            float2 lo = upk(accL), hi = upk(accH);
            *(float4*)(obase + (size_t)ci*HW + (H0 + Nh)*512 + W0) =
                make_float4(lo.x, lo.y, hi.x, hi.y);
        }
    }
}

// ---------------- launch -----------------------------------------------------
extern "C" void kernel_launch(void* const* d_in, const int* in_sizes, int n_in,
                              void* d_out, int out_size) {
    const float* x      = (const float*)d_in[0];
    const float* qkv_w  = (const float*)d_in[1];
    const float* dw_w   = (const float*)d_in[2];
    const float* proj_w = (const float*)d_in[3];
    const float* temp   = (const float*)d_in[4];
    float* out = (float*)d_out;
    (void)in_sizes; (void)n_in; (void)out_size;

    void *p_qkv, *p_ao;
    cudaGetSymbolAddress(&p_qkv, g_qkv);
    cudaGetSymbolAddress(&p_ao,  g_ao);

    cudaFuncSetAttribute(k_gram_mma, cudaFuncAttributeMaxDynamicSharedMemorySize,
                         GRAM_SMEM);

    k_zero<<<12, 256>>>();
    k_conv1x1<<<dim3(2048, 3, 2), 128>>>(x, qkv_w, (float*)p_qkv, 144);
    k_dw<<<dim3(512, 144, 2), 128>>>(dw_w);
    k_gram_mma<<<dim3(32, 16), 192, GRAM_SMEM>>>();
    k_soft<<<192, 256>>>(temp);
    k_attnv<<<dim3(64, 16), 256>>>();
    k_conv1x1<<<dim3(2048, 1, 2), 128>>>((const float*)p_ao, proj_w, out, 48);
}

// round 13
// speedup vs baseline: 1.6612x; 1.0766x over previous
#include <cuda_runtime.h>
#include <cuda_bf16.h>
#include <math.h>
#include <stdint.h>

#define HW 262144   // 512*512
typedef unsigned long long u64;

// ---------------- packed f32x2 helpers (sm_103a FFMA2) ------------------------
__device__ __forceinline__ u64 pk(float lo, float hi) {
    u64 r;
    asm("mov.b64 %0, {%1, %2};" : "=l"(r) : "f"(lo), "f"(hi));
    return r;
}
__device__ __forceinline__ void fma2(u64& d, u64 a, u64 b) {
    asm("fma.rn.f32x2 %0, %1, %2, %0;" : "+l"(d) : "l"(a), "l"(b));
}
__device__ __forceinline__ float2 upk(u64 v) {
    float2 f;
    asm("mov.b64 {%0, %1}, %2;" : "=f"(f.x), "=f"(f.y) : "l"(v));
    return f;
}

// ---------------- mma.sync helper (bf16, fp32 accum) --------------------------
__device__ __forceinline__ void mma16816(float* c, const uint32_t* a, const uint32_t* b) {
    asm volatile(
        "mma.sync.aligned.m16n8k16.row.col.f32.bf16.bf16.f32 "
        "{%0,%1,%2,%3}, {%4,%5,%6,%7}, {%8,%9}, {%0,%1,%2,%3};"
        : "+f"(c[0]), "+f"(c[1]), "+f"(c[2]), "+f"(c[3])
        : "r"(a[0]), "r"(a[1]), "r"(a[2]), "r"(a[3]), "r"(b[0]), "r"(b[1]));
}
__device__ __forceinline__ uint32_t pack_bf16x2(float a, float b) {
    return (uint32_t)__bfloat16_as_ushort(__float2bfloat16(a))
         | ((uint32_t)__bfloat16_as_ushort(__float2bfloat16(b)) << 16);
}

// ---------------- scratch (device globals; no allocation allowed) -------------
__device__ float g_qkv   [2*144*HW];    // after 1x1 conv
__device__ float g_dwo   [2*144*HW];    // after depthwise 3x3
__device__ float g_ao    [2*48*HW];     // attn @ v, image layout
__device__ float g_sq    [2*2*48*16];   // sum of squares: [b][q/k][ch][phase]
__device__ float g_gsplit[32*16*96*96]; // per-split partial grams
__device__ __nv_bfloat16 g_attn_h[16*96*96];  // softmaxed attn hi, row-major [r][d]
__device__ __nv_bfloat16 g_attn_l[16*96*96];  // softmaxed attn lo

// ---------------- zero sum-of-squares accumulator -----------------------------
__global__ void k_zero() {
    int i = blockIdx.x * 256 + threadIdx.x;
    if (i < 2*2*48*16) g_sq[i] = 0.f;
}

// ---------------- qkv 1x1 conv via mma.sync (hi/lo split W and X) -------------
// grid (1024, 2), block 288 (9 warps = 9 oc-tiles of 16).  N = 256 px per CTA.
#define CPW 28                               // padded words per K row (24 used)
#define C_WH 0
#define C_WL (144*CPW)                       // 4032
#define C_XH (2*144*CPW)                     // 8064
#define C_XL (2*144*CPW + 256*CPW)           // 15232
#define CONV_SMEM ((2*144*CPW + 2*256*CPW)*4)  // 89600 bytes

__global__ __launch_bounds__(288) void k_conv_mma(const float* __restrict__ x,
                                                  const float* __restrict__ wgt) {
    extern __shared__ uint32_t swc[];
    const int tid = threadIdx.x;
    const int wid = tid >> 5, lane = tid & 31;
    const int px0 = blockIdx.x * 256;
    const int b   = blockIdx.y;
    const float* inb = x + (size_t)b * 48 * HW;

    // A fill: weights [144][48] -> hi/lo bf16, row-major padded
    {
        __nv_bfloat16* wh = (__nv_bfloat16*)(swc + C_WH);
        __nv_bfloat16* wl = (__nv_bfloat16*)(swc + C_WL);
        for (int i = tid; i < 144*48; i += 288) {
            int oc = i / 48, ci = i - oc*48;
            float v = wgt[i];
            __nv_bfloat16 hi = __float2bfloat16(v);
            wh[oc*(2*CPW) + ci] = hi;
            wl[oc*(2*CPW) + ci] = __float2bfloat16(v - __bfloat162float(hi));
        }
    }
    // B fill: x tile [48 ch][256 px] -> [px][ch] hi/lo bf16
    {
        __nv_bfloat16* xh = (__nv_bfloat16*)(swc + C_XH);
        __nv_bfloat16* xl = (__nv_bfloat16*)(swc + C_XL);
        for (int i = tid; i < 48*64; i += 288) {
            int ch = i >> 6, p4 = i & 63;
            float4 v4 = ((const float4*)(inb + (size_t)ch*HW + px0))[p4];
            float vv[4] = {v4.x, v4.y, v4.z, v4.w};
#pragma unroll
            for (int t = 0; t < 4; t++) {
                float v = vv[t];
                __nv_bfloat16 hi = __float2bfloat16(v);
                xh[(p4*4 + t)*(2*CPW) + ch] = hi;
                xl[(p4*4 + t)*(2*CPW) + ch] = __float2bfloat16(v - __bfloat162float(hi));
            }
        }
    }
    __syncthreads();

    const int g4 = lane >> 2, q4 = lane & 3;
    const int arow = wid*16 + g4;

#pragma unroll 1
    for (int half = 0; half < 2; half++) {
        float acc[16][4];
#pragma unroll
        for (int t = 0; t < 16; t++)
#pragma unroll
            for (int i = 0; i < 4; i++) acc[t][i] = 0.f;

#pragma unroll
        for (int ks = 0; ks < 3; ks++) {
            const int kw = ks*8 + q4;
            uint32_t Ah[4], Al[4];
            Ah[0] = swc[C_WH +  arow     *CPW + kw    ];
            Ah[1] = swc[C_WH + (arow + 8)*CPW + kw    ];
            Ah[2] = swc[C_WH +  arow     *CPW + kw + 4];
            Ah[3] = swc[C_WH + (arow + 8)*CPW + kw + 4];
            Al[0] = swc[C_WL +  arow     *CPW + kw    ];
            Al[1] = swc[C_WL + (arow + 8)*CPW + kw    ];
            Al[2] = swc[C_WL +  arow     *CPW + kw + 4];
            Al[3] = swc[C_WL + (arow + 8)*CPW + kw + 4];
#pragma unroll
            for (int nt = 0; nt < 16; nt++) {
                const int nrow = (half*16 + nt)*8 + g4;
                uint32_t Bh[2], Bl[2];
                Bh[0] = swc[C_XH + nrow*CPW + kw    ];
                Bh[1] = swc[C_XH + nrow*CPW + kw + 4];
                Bl[0] = swc[C_XL + nrow*CPW + kw    ];
                Bl[1] = swc[C_XL + nrow*CPW + kw + 4];
                mma16816(acc[nt], Ah, Bh);
                mma16816(acc[nt], Ah, Bl);
                mma16816(acc[nt], Al, Bh);
            }
        }
#pragma unroll
        for (int nt = 0; nt < 16; nt++) {
            const int col = px0 + (half*16 + nt)*8 + q4*2;
            float* o1 = g_qkv + ((size_t)b*144 + arow)*HW + col;
            *(float2*)o1 = make_float2(acc[nt][0], acc[nt][1]);
            *(float2*)(o1 + (size_t)8*HW) = make_float2(acc[nt][2], acc[nt][3]);
        }
    }
}

// ---------------- 1x1 conv as SGEMM (f32x2) — used for proj -------------------
__global__ __launch_bounds__(128) void k_conv1x1(const float* __restrict__ in,
                                                 const float* __restrict__ wgt,
                                                 float* __restrict__ out,
                                                 int ocTot) {
    __shared__ __align__(16) float s_x[48*128];
    __shared__ float s_w[48*48];
    const int tid = threadIdx.x;
    const int px0 = blockIdx.x * 128;
    const int ocb = blockIdx.y * 48;
    const int b   = blockIdx.z;
    const float* inb = in + (size_t)b * 48 * HW;

    for (int i = tid; i < 48*48; i += 128) {
        int oc = i / 48, ci = i - oc*48;
        s_w[ci*48 + oc] = wgt[(ocb + oc)*48 + ci];
    }
    for (int i = tid; i < 48*32; i += 128) {
        int ci = i >> 5, p4 = i & 31;
        ((float4*)s_x)[i] = ((const float4*)(inb + (size_t)ci*HW + px0))[p4];
    }
    __syncthreads();

    const int ty = tid >> 4, tx = tid & 15;
    u64 acc2[6][4];
#pragma unroll
    for (int i = 0; i < 6; i++)
#pragma unroll
        for (int j = 0; j < 4; j++) acc2[i][j] = pk(0.f, 0.f);

    for (int ci = 0; ci < 48; ci++) {
        u64 wp[6], xv[4];
#pragma unroll
        for (int i = 0; i < 6; i++) {
            float wv = s_w[ci*48 + ty*6 + i];
            wp[i] = pk(wv, wv);
        }
#pragma unroll
        for (int j = 0; j < 4; j++)
            xv[j] = *(const u64*)&s_x[ci*128 + tx*2 + j*32];
#pragma unroll
        for (int i = 0; i < 6; i++)
#pragma unroll
            for (int j = 0; j < 4; j++) fma2(acc2[i][j], wp[i], xv[j]);
    }

#pragma unroll
    for (int i = 0; i < 6; i++) {
        float* op = out + ((size_t)b*ocTot + ocb + ty*6 + i)*HW + px0;
#pragma unroll
        for (int j = 0; j < 4; j++)
            *(float2*)(op + tx*2 + j*32) = upk(acc2[i][j]);
    }
}

// ---------------- depthwise 3x3 (zero pad) + fused phase sum-of-squares -------
__global__ __launch_bounds__(128) void k_dw(const float* __restrict__ dww) {
    __shared__ float s_red[4][4];
    const int y  = blockIdx.x;
    const int ch = blockIdx.y;
    const int b  = blockIdx.z;
    const float* in  = g_qkv + (size_t)(b*144 + ch) * HW;
    float*       out = g_dwo + (size_t)(b*144 + ch) * HW;
    float w[9];
#pragma unroll
    for (int i = 0; i < 9; i++) w[i] = dww[ch*9 + i];

    const int x4 = threadIdx.x * 4;
    float o0 = 0.f, o1 = 0.f, o2 = 0.f, o3 = 0.f;
#pragma unroll
    for (int dy = -1; dy <= 1; dy++) {
        int yy = y + dy;
        if (yy < 0 || yy >= 512) continue;
        const float* row = in + yy*512;
        float4 c = *(const float4*)(row + x4);
        float l = (x4 > 0)   ? row[x4 - 1] : 0.f;
        float r = (x4 < 508) ? row[x4 + 4] : 0.f;
        float w0 = w[(dy+1)*3], w1 = w[(dy+1)*3 + 1], w2 = w[(dy+1)*3 + 2];
        o0 += w0*l   + w1*c.x + w2*c.y;
        o1 += w0*c.x + w1*c.y + w2*c.z;
        o2 += w0*c.y + w1*c.z + w2*c.w;
        o3 += w0*c.z + w1*c.w + w2*r;
    }
    *(float4*)(out + y*512 + x4) = make_float4(o0, o1, o2, o3);

    if (ch < 96) {
        float s0 = o0*o0, s1 = o1*o1, s2 = o2*o2, s3 = o3*o3;
#pragma unroll
        for (int o = 16; o > 0; o >>= 1) {
            s0 += __shfl_xor_sync(0xffffffffu, s0, o);
            s1 += __shfl_xor_sync(0xffffffffu, s1, o);
            s2 += __shfl_xor_sync(0xffffffffu, s2, o);
            s3 += __shfl_xor_sync(0xffffffffu, s3, o);
        }
        int warp = threadIdx.x >> 5, lane = threadIdx.x & 31;
        if (lane == 0) {
            s_red[warp][0] = s0; s_red[warp][1] = s1;
            s_red[warp][2] = s2; s_red[warp][3] = s3;
        }
        __syncthreads();
        if (threadIdx.x < 4) {
            float v = s_red[0][threadIdx.x] + s_red[1][threadIdx.x]
                    + s_red[2][threadIdx.x] + s_red[3][threadIdx.x];
            int qk = ch / 48, cc = ch - qk*48;
            atomicAdd(&g_sq[((b*2 + qk)*48 + cc)*16 + (y & 3)*4 + threadIdx.x], v);
        }
    }
}

// ---------------- gram via mma.sync bf16 hi/lo split --------------------------
#define GT_STRIDE 72
#define GT_WORDS  36
#define GT_BYTES  (96*GT_STRIDE*2)
#define OFF_QH 0
#define OFF_QL GT_BYTES
#define OFF_KH (2*GT_BYTES)
#define OFF_KL (3*GT_BYTES)
#define GRAM_SMEM (4*GT_BYTES)

__global__ __launch_bounds__(192) void k_gram_mma() {
    extern __shared__ char smem[];
    uint32_t* sw = (uint32_t*)smem;
    const int tid  = threadIdx.x;
    const int wid  = tid >> 5, lane = tid & 31;
    const int split = blockIdx.x;
    const int bh = blockIdx.y;
    const int b = bh >> 3, h = bh & 7;
    const float* qbase = g_dwo + (size_t)(b*144      + h*6) * HW;
    const float* kbase = g_dwo + (size_t)(b*144 + 48 + h*6) * HW;

    float acc[12][4];
#pragma unroll
    for (int t = 0; t < 12; t++)
#pragma unroll
        for (int i = 0; i < 4; i++) acc[t][i] = 0.f;

    const int g4 = lane >> 2;
    const int q4 = lane & 3;

#pragma unroll 1
    for (int chunk = 0; chunk < 8; chunk++) {
        const int n0 = split*512 + chunk*64;
        const int hb = n0 >> 7, wb = n0 & 127;

        if (chunk > 0) __syncthreads();
#pragma unroll
        for (int i = 0; i < 16; i++) {
            int u = tid + i*192;
            int side = (u >= 1536) ? 1 : 0;
            int rem = u - side*1536;
            int j = rem & 63, g = rem >> 6;
            int ci = g >> 2, phy = g & 3;
            const float* bp = side ? kbase : qbase;
            float4 v4 = *(const float4*)(bp + (size_t)ci*HW
                                            + (size_t)(4*hb + phy)*512 + 4*(wb + j));
            __nv_bfloat16* th = (__nv_bfloat16*)(smem + (side ? OFF_KH : OFF_QH));
            __nv_bfloat16* tl = (__nv_bfloat16*)(smem + (side ? OFF_KL : OFF_QL));
            int r0 = ci*16 + phy*4;
            float vv[4] = {v4.x, v4.y, v4.z, v4.w};
#pragma unroll
            for (int p = 0; p < 4; p++) {
                float v = vv[p];
                __nv_bfloat16 hi = __float2bfloat16(v);
                __nv_bfloat16 lo = __float2bfloat16(v - __bfloat162float(hi));
                th[(r0 + p)*GT_STRIDE + j] = hi;
                tl[(r0 + p)*GT_STRIDE + j] = lo;
            }
        }
        __syncthreads();

        const uint32_t* qh = sw + (OFF_QH >> 2);
        const uint32_t* ql = sw + (OFF_QL >> 2);
        const uint32_t* kh = sw + (OFF_KH >> 2);
        const uint32_t* kl = sw + (OFF_KL >> 2);
        const int arow = wid*16 + g4;
#pragma unroll
        for (int ks = 0; ks < 4; ks++) {
            const int kw = ks*8 + q4;
            uint32_t Ah[4], Al[4];
            Ah[0] = qh[ arow     *GT_WORDS + kw    ];
            Ah[1] = qh[(arow + 8)*GT_WORDS + kw    ];
            Ah[2] = qh[ arow     *GT_WORDS + kw + 4];
            Ah[3] = qh[(arow + 8)*GT_WORDS + kw + 4];
            Al[0] = ql[ arow     *GT_WORDS + kw    ];
            Al[1] = ql[(arow + 8)*GT_WORDS + kw    ];
            Al[2] = ql[ arow     *GT_WORDS + kw + 4];
            Al[3] = ql[(arow + 8)*GT_WORDS + kw + 4];
#pragma unroll
            for (int nt = 0; nt < 12; nt++) {
                const int nrow = nt*8 + g4;
                uint32_t Bh[2], Bl[2];
                Bh[0] = kh[nrow*GT_WORDS + kw    ];
                Bh[1] = kh[nrow*GT_WORDS + kw + 4];
                Bl[0] = kl[nrow*GT_WORDS + kw    ];
                Bl[1] = kl[nrow*GT_WORDS + kw + 4];
                mma16816(acc[nt], Ah, Bh);
                mma16816(acc[nt], Ah, Bl);
                mma16816(acc[nt], Al, Bh);
            }
        }
    }

    float* gp = g_gsplit + (size_t)(split*16 + bh)*96*96;
    const int r0 = wid*16 + g4;
#pragma unroll
    for (int nt = 0; nt < 12; nt++) {
        const int c = nt*8 + q4*2;
        *(float2*)(gp + (size_t) r0     *96 + c) = make_float2(acc[nt][0], acc[nt][1]);
        *(float2*)(gp + (size_t)(r0 + 8)*96 + c) = make_float2(acc[nt][2], acc[nt][3]);
    }
}

// ---------------- softmax -> bf16 hi/lo attention, row-major [r][d] -----------
__global__ __launch_bounds__(256) void k_soft(const float* __restrict__ temp) {
    const int warp = blockIdx.x * 8 + (threadIdx.x >> 5);
    const int lane = threadIdx.x & 31;
    const int r = warp % 96, bh = warp / 96;
    const int b = bh >> 3, h = bh & 7;
    const float t = temp[h];
    float sqq = g_sq[((b*2 + 0)*48 + h*6 + (r >> 4))*16 + (r & 15)];
    const float invq = 1.f / fmaxf(sqrtf(sqq), 1e-12f);

    float v[3];
    float mx = -1e30f;
#pragma unroll
    for (int j = 0; j < 3; j++) {
        int d = lane + j*32;
        float g = 0.f;
#pragma unroll 4
        for (int s = 0; s < 32; s++)
            g += g_gsplit[((size_t)(s*16 + bh)*96 + r)*96 + d];
        float sqk = g_sq[((b*2 + 1)*48 + h*6 + (d >> 4))*16 + (d & 15)];
        float invk = 1.f / fmaxf(sqrtf(sqk), 1e-12f);
        v[j] = g * invq * invk * t;
        mx = fmaxf(mx, v[j]);
    }
#pragma unroll
    for (int o = 16; o > 0; o >>= 1) mx = fmaxf(mx, __shfl_xor_sync(0xffffffffu, mx, o));
    float sum = 0.f;
#pragma unroll
    for (int j = 0; j < 3; j++) { v[j] = __expf(v[j] - mx); sum += v[j]; }
#pragma unroll
    for (int o = 16; o > 0; o >>= 1) sum += __shfl_xor_sync(0xffffffffu, sum, o);
    float inv = 1.f / sum;
    __nv_bfloat16* ah = g_attn_h + (size_t)bh*96*96 + (size_t)r*96;
    __nv_bfloat16* al = g_attn_l + (size_t)bh*96*96 + (size_t)r*96;
#pragma unroll
    for (int j = 0; j < 3; j++) {
        int d = lane + j*32;
        float a = v[j] * inv;
        __nv_bfloat16 hi = __float2bfloat16(a);
        ah[d] = hi;
        al[d] = __float2bfloat16(a - __bfloat162float(hi));
    }
}

// ---------------- attn @ v via mma.sync (hi/lo split) -------------------------
// grid (128 chunks of 128 tokens, 16 bh), block 192 (6 warps = 6 r-tiles).
#define APW 52                                  // padded words per row (48 used)
#define AV_AH 0
#define AV_AL (96*APW)                          // 4992 words
#define AV_VH (2*96*APW)                        // 9984
#define AV_VL (2*96*APW + 128*APW)              // 16640
#define AV_SMEM ((2*96*APW + 2*128*APW)*4)      // 93184 bytes

__global__ __launch_bounds__(192) void k_attnv_mma() {
    extern __shared__ uint32_t swa[];
    const int tid = threadIdx.x;
    const int wid = tid >> 5, lane = tid & 31;
    const int hb = blockIdx.x;                   // token chunk = h-block row
    const int bh = blockIdx.y;
    const int b = bh >> 3, h = bh & 7;
    const float* vbase = g_dwo + (size_t)(b*144 + 96 + h*6) * HW;

    // A fill: attn hi/lo bf16 [96][96] -> padded rows
    {
        const uint32_t* srcH = (const uint32_t*)(g_attn_h + (size_t)bh*96*96);
        const uint32_t* srcL = (const uint32_t*)(g_attn_l + (size_t)bh*96*96);
        for (int i = tid; i < 96*48; i += 192) {
            int row = i / 48, w = i - row*48;
            swa[AV_AH + row*APW + w] = srcH[i];
            swa[AV_AL + row*APW + w] = srcL[i];
        }
    }
    // V fill: 128 tokens x 96 d (float4 = 4 consecutive d of one token)
    for (int i = tid; i < 3072; i += 192) {
        int j = i & 127, g = i >> 7;             // g 0..23
        int ci = g >> 2, phy = g & 3;
        float4 v4 = *(const float4*)(vbase + (size_t)ci*HW
                                        + (size_t)(4*hb + phy)*512 + 4*j);
        __nv_bfloat16 h0 = __float2bfloat16(v4.x);
        __nv_bfloat16 h1 = __float2bfloat16(v4.y);
        __nv_bfloat16 h2 = __float2bfloat16(v4.z);
        __nv_bfloat16 h3 = __float2bfloat16(v4.w);
        uint32_t hA = (uint32_t)__bfloat16_as_ushort(h0)
                    | ((uint32_t)__bfloat16_as_ushort(h1) << 16);
        uint32_t hB = (uint32_t)__bfloat16_as_ushort(h2)
                    | ((uint32_t)__bfloat16_as_ushort(h3) << 16);
        uint32_t lA = pack_bf16x2(v4.x - __bfloat162float(h0),
                                  v4.y - __bfloat162float(h1));
        uint32_t lB = pack_bf16x2(v4.z - __bfloat162float(h2),
                                  v4.w - __bfloat162float(h3));
        int w0 = j*APW + (ci*16 + phy*4)/2;      // word offset (8B aligned)
        swa[AV_VH + w0] = hA; swa[AV_VH + w0 + 1] = hB;
        swa[AV_VL + w0] = lA; swa[AV_VL + w0 + 1] = lB;
    }
    __syncthreads();

    const int g4 = lane >> 2, q4 = lane & 3;
    const int arow = wid*16 + g4;

    float acc[16][4];
#pragma unroll
    for (int t = 0; t < 16; t++)
#pragma unroll
        for (int i = 0; i < 4; i++) acc[t][i] = 0.f;

#pragma unroll
    for (int ks = 0; ks < 6; ks++) {
        const int kw = ks*8 + q4;
        uint32_t Ah[4], Al[4];
        Ah[0] = swa[AV_AH +  arow     *APW + kw    ];
        Ah[1] = swa[AV_AH + (arow + 8)*APW + kw    ];
        Ah[2] = swa[AV_AH +  arow     *APW + kw + 4];
        Ah[3] = swa[AV_AH + (arow + 8)*APW + kw + 4];
        Al[0] = swa[AV_AL +  arow     *APW + kw    ];
        Al[1] = swa[AV_AL + (arow + 8)*APW + kw    ];
        Al[2] = swa[AV_AL +  arow     *APW + kw + 4];
        Al[3] = swa[AV_AL + (arow + 8)*APW + kw + 4];
#pragma unroll
        for (int nt = 0; nt < 16; nt++) {
            const int nrow = nt*8 + g4;
            uint32_t Bh[2], Bl[2];
            Bh[0] = swa[AV_VH + nrow*APW + kw    ];
            Bh[1] = swa[AV_VH + nrow*APW + kw + 4];
            Bl[0] = swa[AV_VL + nrow*APW + kw    ];
            Bl[1] = swa[AV_VL + nrow*APW + kw + 4];
            mma16816(acc[nt], Ah, Bh);
            mma16816(acc[nt], Ah, Bl);
            mma16816(acc[nt], Al, Bh);
        }
    }

    // stage fragments into smem [token][r] (reuse V region), then coalesced out
    __syncthreads();
    float* so = (float*)(swa + AV_VH);           // [128][104]
#pragma unroll
    for (int nt = 0; nt < 16; nt++) {
        const int n0 = nt*8 + q4*2;
        so[ n0     *104 + arow    ] = acc[nt][0];
        so[(n0 + 1)*104 + arow    ] = acc[nt][1];
        so[ n0     *104 + arow + 8] = acc[nt][2];
        so[(n0 + 1)*104 + arow + 8] = acc[nt][3];
    }
    __syncthreads();

    if (tid < 128) {
        const int j = tid;
        const int W0 = 4*j;
        float* obase = g_ao + (size_t)(b*48 + h*6) * HW;
#pragma unroll
        for (int ci = 0; ci < 6; ci++)
#pragma unroll
            for (int nh = 0; nh < 4; nh++) {
                float4 v = *(float4*)&so[j*104 + ci*16 + nh*4];
                *(float4*)(obase + (size_t)ci*HW + (size_t)(4*hb + nh)*512 + W0) = v;
            }
    }
}

// ---------------- launch -----------------------------------------------------
extern "C" void kernel_launch(void* const* d_in, const int* in_sizes, int n_in,
                              void* d_out, int out_size) {
    const float* x      = (const float*)d_in[0];
    const float* qkv_w  = (const float*)d_in[1];
    const float* dw_w   = (const float*)d_in[2];
    const float* proj_w = (const float*)d_in[3];
    const float* temp   = (const float*)d_in[4];
    float* out = (float*)d_out;
    (void)in_sizes; (void)n_in; (void)out_size;

    void* p_ao;
    cudaGetSymbolAddress(&p_ao, g_ao);

    cudaFuncSetAttribute(k_gram_mma,  cudaFuncAttributeMaxDynamicSharedMemorySize, GRAM_SMEM);
    cudaFuncSetAttribute(k_conv_mma,  cudaFuncAttributeMaxDynamicSharedMemorySize, CONV_SMEM);
    cudaFuncSetAttribute(k_attnv_mma, cudaFuncAttributeMaxDynamicSharedMemorySize, AV_SMEM);

    k_zero<<<12, 256>>>();
    k_conv_mma<<<dim3(1024, 2), 288, CONV_SMEM>>>(x, qkv_w);
    k_dw<<<dim3(512, 144, 2), 128>>>(dw_w);
    k_gram_mma<<<dim3(32, 16), 192, GRAM_SMEM>>>();
    k_soft<<<192, 256>>>(temp);
    k_attnv_mma<<<dim3(128, 16), 192, AV_SMEM>>>();
    k_conv1x1<<<dim3(2048, 1, 2), 128>>>((const float*)p_ao, proj_w, out, 48);
}